// round 6
// baseline (speedup 1.0000x reference)
#include <cuda_runtime.h>
#include <math.h>

#define BB 8
#define NPTS 2048
#define NPAIR 1024
#define NTHREADS 512
#define NCHUNK 32                 // 64 j per chunk

// warm kernel config (1 CTA/SM, 8 rows/warp)
#define WARM_ROWS_CTA 128
#define WARM_CHUNKS 16
// fast kernel config (2 CTA/SM, 4 rows/warp)
#define FAST_ROWS_CTA 64
#define FAST_CHUNKS 32

// eps = 0.005
#define KLOG 288.53900817779268f          // log2(e)/eps
#define EPSLN2 0.0034657359027997266f     // eps*ln2  (= 1/KLOG)
#define ACONST (-0.038123094930796993f)   // eps*log(1/N)
#define SKIP_THR (-30.0f)

typedef unsigned long long u64;

__device__ __forceinline__ float ex2f(float x) {
    float r;
    asm("ex2.approx.ftz.f32 %0, %1;" : "=f"(r) : "f"(x));
    return r;
}
__device__ __forceinline__ u64 pack2(float lo, float hi) {
    u64 r; asm("mov.b64 %0, {%1, %2};" : "=l"(r) : "f"(lo), "f"(hi)); return r;
}
__device__ __forceinline__ void unpack2(u64 v, float& lo, float& hi) {
    asm("mov.b64 {%0, %1}, %2;" : "=f"(lo), "=f"(hi) : "l"(v));
}
__device__ __forceinline__ u64 fma2(u64 a, u64 b, u64 c) {
    u64 r; asm("fma.rn.f32x2 %0, %1, %2, %3;" : "=l"(r) : "l"(a), "l"(b), "l"(c)); return r;
}
__device__ __forceinline__ u64 add2(u64 a, u64 b) {
    u64 r; asm("add.rn.f32x2 %0, %1, %2;" : "=l"(r) : "l"(a), "l"(b)); return r;
}

// Persistent scratch (device globals: allowed; cudaMalloc is not)
__device__ float  g_p1[BB * NPTS * 3];
__device__ float  g_p2[BB * NPTS * 3];
__device__ float4 g_lo1[BB * NCHUNK], g_hi1[BB * NCHUNK];
__device__ float4 g_lo2[BB * NCHUNK], g_hi2[BB * NCHUNK];
__device__ float  g_f[BB * NPTS];
__device__ float  g_g[BB * NPTS];
__device__ float  g_mf[BB * NPTS];
__device__ float  g_mg[BB * NPTS];
__device__ float  g_partial[BB * FAST_CHUNKS];

__global__ void init_kernel() {
    int i = blockIdx.x * blockDim.x + threadIdx.x;
    if (i < BB * NPTS) g_g[i] = 0.0f;
}

__device__ __forceinline__ unsigned expand_bits(unsigned v) {
    v &= 0x3FFu;
    v = (v | (v << 16)) & 0x030000FFu;
    v = (v | (v << 8))  & 0x0300F00Fu;
    v = (v | (v << 4))  & 0x030C30C3u;
    v = (v | (v << 2))  & 0x09249249u;
    return v;
}

// One CTA per batch: Morton bitonic sort + per-chunk AABB.
__global__ __launch_bounds__(NTHREADS, 1)
void sort_kernel(const float* __restrict__ pts, int side)
{
    __shared__ unsigned key[NPTS];
    __shared__ int      idx[NPTS];
    const int b = blockIdx.x, tid = threadIdx.x;
    const float* p = pts + b * NPTS * 3;

    for (int j = tid; j < NPTS; j += NTHREADS) {
        float x = p[3*j], y = p[3*j+1], z = p[3*j+2];
        unsigned qx = (unsigned)fminf(fmaxf(x * 1024.0f, 0.0f), 1023.0f);
        unsigned qy = (unsigned)fminf(fmaxf(y * 1024.0f, 0.0f), 1023.0f);
        unsigned qz = (unsigned)fminf(fmaxf(z * 1024.0f, 0.0f), 1023.0f);
        key[j] = expand_bits(qx) | (expand_bits(qy) << 1) | (expand_bits(qz) << 2);
        idx[j] = j;
    }
    __syncthreads();

    for (int k2 = 2; k2 <= NPTS; k2 <<= 1) {
        for (int j2 = k2 >> 1; j2 > 0; j2 >>= 1) {
            for (int i = tid; i < NPTS; i += NTHREADS) {
                int l = i ^ j2;
                if (l > i) {
                    bool up = ((i & k2) == 0);
                    unsigned ki = key[i], kl = key[l];
                    bool swp = up ? (ki > kl) : (ki < kl);
                    if (swp) {
                        key[i] = kl; key[l] = ki;
                        int t = idx[i]; idx[i] = idx[l]; idx[l] = t;
                    }
                }
            }
            __syncthreads();
        }
    }

    float* out = (side ? g_p2 : g_p1) + b * NPTS * 3;
    for (int k = tid; k < NPTS; k += NTHREADS) {
        int s = idx[k];
        out[3*k]   = p[3*s];
        out[3*k+1] = p[3*s+1];
        out[3*k+2] = p[3*s+2];
    }
    __syncthreads();

    if (tid < NCHUNK) {
        float lx = 1e30f, ly = 1e30f, lz = 1e30f;
        float hx = -1e30f, hy = -1e30f, hz = -1e30f;
        for (int k = 0; k < 64; k++) {
            int j = tid * 64 + k;
            float x = out[3*j], y = out[3*j+1], z = out[3*j+2];
            lx = fminf(lx, x); hx = fmaxf(hx, x);
            ly = fminf(ly, y); hy = fmaxf(hy, y);
            lz = fminf(lz, z); hz = fmaxf(hz, z);
        }
        float4* glo = side ? g_lo2 : g_lo1;
        float4* ghi = side ? g_hi2 : g_hi1;
        glo[b * NCHUNK + tid] = make_float4(lx, ly, lz, 0.0f);
        ghi[b * NCHUNK + tid] = make_float4(hx, hy, hz, 0.0f);
    }
}

// ---------- Warmup: rigorous two-pass half-step (emits row max) ----------
__global__ __launch_bounds__(NTHREADS, 1)
void sink_warm(int dir)
{
    __shared__ float4 sA[NPAIR];
    __shared__ float4 sB[NPAIR];

    const int b = blockIdx.y, tid = threadIdx.x;
    const float* rowPts = dir ? g_p2 : g_p1;
    const float* colPts = dir ? g_p1 : g_p2;
    const float* colPot = dir ? g_f  : g_g;
    float*       outPot = dir ? g_g  : g_f;
    float*       outM   = dir ? g_mg : g_mf;

    const float* cp = colPts + b * NPTS * 3;
    const float* gp = colPot + b * NPTS;
    for (int p = tid; p < NPAIR; p += NTHREADS) {
        int j = 2 * p;
        float a0 = cp[3*j],   a1 = cp[3*j+1], a2 = cp[3*j+2];
        float b0 = cp[3*j+3], b1 = cp[3*j+4], b2 = cp[3*j+5];
        float ha = (gp[j]   - (a0*a0 + a1*a1 + a2*a2)) * KLOG;
        float hb = (gp[j+1] - (b0*b0 + b1*b1 + b2*b2)) * KLOG;
        sA[p] = make_float4(a0, b0, a1, b1);
        sB[p] = make_float4(a2, b2, ha, hb);
    }
    __syncthreads();

    const int warp = tid >> 5, lane = tid & 31;
    const int row0 = blockIdx.x * WARM_ROWS_CTA + warp * 8;
    const float* rp = rowPts + b * NPTS * 3;

    u64 X0b[8], X1b[8], X2b[8];
    float xx[8], m[8];
    #pragma unroll
    for (int r = 0; r < 8; r++) {
        int i = row0 + r;
        float x0 = rp[3*i], x1 = rp[3*i+1], x2 = rp[3*i+2];
        xx[r] = x0*x0 + x1*x1 + x2*x2;
        X0b[r] = pack2(2.0f*KLOG*x0, 2.0f*KLOG*x0);
        X1b[r] = pack2(2.0f*KLOG*x1, 2.0f*KLOG*x1);
        X2b[r] = pack2(2.0f*KLOG*x2, 2.0f*KLOG*x2);
        m[r]  = -1e30f;
    }

    unsigned int aA0 = (unsigned int)__cvta_generic_to_shared(sA) + lane * 16u;
    unsigned int aB0 = (unsigned int)__cvta_generic_to_shared(sB) + lane * 16u;

    {
        unsigned int aA = aA0, aB = aB0;
        #pragma unroll 2
        for (int it = 0; it < NPAIR / 32; it++) {
            u64 y0p, y1p, y2p, hp;
            asm("ld.shared.v2.b64 {%0, %1}, [%2];" : "=l"(y0p), "=l"(y1p) : "r"(aA));
            asm("ld.shared.v2.b64 {%0, %1}, [%2];" : "=l"(y2p), "=l"(hp)  : "r"(aB));
            #pragma unroll
            for (int r = 0; r < 8; r++) {
                u64 w = fma2(X0b[r], y0p, fma2(X1b[r], y1p, fma2(X2b[r], y2p, hp)));
                float wl, wh; unpack2(w, wl, wh);
                m[r] = fmaxf(m[r], fmaxf(wl, wh));
            }
            aA += 512u; aB += 512u;
        }
    }

    u64 mnegb[8], Sp[8];
    #pragma unroll
    for (int r = 0; r < 8; r++) {
        #pragma unroll
        for (int o = 16; o; o >>= 1)
            m[r] = fmaxf(m[r], __shfl_xor_sync(0xffffffffu, m[r], o));
        mnegb[r] = pack2(-m[r], -m[r]);
        Sp[r] = 0ull;
    }

    {
        unsigned int aA = aA0, aB = aB0;
        #pragma unroll 2
        for (int it = 0; it < NPAIR / 32; it++) {
            u64 y0p, y1p, y2p, hp;
            asm("ld.shared.v2.b64 {%0, %1}, [%2];" : "=l"(y0p), "=l"(y1p) : "r"(aA));
            asm("ld.shared.v2.b64 {%0, %1}, [%2];" : "=l"(y2p), "=l"(hp)  : "r"(aB));
            #pragma unroll
            for (int r = 0; r < 8; r++) {
                u64 w = fma2(X0b[r], y0p, fma2(X1b[r], y1p, fma2(X2b[r], y2p, hp)));
                u64 t = add2(w, mnegb[r]);
                float tl, th; unpack2(t, tl, th);
                Sp[r] = add2(Sp[r], pack2(ex2f(tl), ex2f(th)));
            }
            aA += 512u; aB += 512u;
        }
    }

    float S[8];
    #pragma unroll
    for (int r = 0; r < 8; r++) {
        float sl, sh; unpack2(Sp[r], sl, sh);
        S[r] = sl + sh;
        #pragma unroll
        for (int o = 16; o; o >>= 1)
            S[r] += __shfl_xor_sync(0xffffffffu, S[r], o);
    }
    if (lane == 0) {
        #pragma unroll
        for (int r = 0; r < 8; r++) {
            outPot[b * NPTS + row0 + r] = ACONST - EPSLN2 * (m[r] + __log2f(S[r])) + xx[r];
            outM[b * NPTS + row0 + r]   = m[r];
        }
    }
}

// ---------- Fast: single-pass, carried max, AABB chunk-mask skip ----------
__global__ __launch_bounds__(NTHREADS, 2)
void sink_fast(int dir)
{
    __shared__ float4 sA[NPAIR];
    __shared__ float4 sB[NPAIR];
    __shared__ float  sHmax[NCHUNK];
    __shared__ float4 sLo[NCHUNK], sHi[NCHUNK];

    const int b = blockIdx.y, tid = threadIdx.x;
    const float* rowPts = dir ? g_p2 : g_p1;
    const float* colPts = dir ? g_p1 : g_p2;
    const float* colPot = dir ? g_f  : g_g;
    float*       outPot = dir ? g_g  : g_f;
    float*       mArr   = dir ? g_mg : g_mf;
    const float4* glo = dir ? g_lo1 : g_lo2;   // columns' boxes
    const float4* ghi = dir ? g_hi1 : g_hi2;

    const int warp = tid >> 5, lane = tid & 31;

    if (tid < NCHUNK) {
        sLo[tid] = glo[b * NCHUNK + tid];
        sHi[tid] = ghi[b * NCHUNK + tid];
    }

    const float* cp = colPts + b * NPTS * 3;
    const float* gp = colPot + b * NPTS;
    #pragma unroll
    for (int k = 0; k < 2; k++) {
        int p = tid + k * NTHREADS;
        int j = 2 * p;
        float a0 = cp[3*j],   a1 = cp[3*j+1], a2 = cp[3*j+2];
        float b0 = cp[3*j+3], b1 = cp[3*j+4], b2 = cp[3*j+5];
        float ha = (gp[j]   - (a0*a0 + a1*a1 + a2*a2)) * KLOG;
        float hb = (gp[j+1] - (b0*b0 + b1*b1 + b2*b2)) * KLOG;
        sA[p] = make_float4(a0, b0, a1, b1);
        sB[p] = make_float4(a2, b2, ha, hb);
        float hm = fmaxf(ha, hb);
        #pragma unroll
        for (int o = 16; o; o >>= 1)
            hm = fmaxf(hm, __shfl_xor_sync(0xffffffffu, hm, o));
        if (lane == 0) sHmax[warp + k * 16] = hm;   // warp covers exactly chunk warp+16k
    }
    __syncthreads();

    const int row0 = blockIdx.x * FAST_ROWS_CTA + warp * 4;
    const float* rp = rowPts + b * NPTS * 3;

    u64 X0b[4], X1b[4], X2b[4], negMb[4], Sp[4];
    float mrun[4];
    #pragma unroll
    for (int r = 0; r < 4; r++) {
        int i = row0 + r;
        float x0 = rp[3*i], x1 = rp[3*i+1], x2 = rp[3*i+2];
        X0b[r] = pack2(2.0f*KLOG*x0, 2.0f*KLOG*x0);
        X1b[r] = pack2(2.0f*KLOG*x1, 2.0f*KLOG*x1);
        X2b[r] = pack2(2.0f*KLOG*x2, 2.0f*KLOG*x2);
        float mp = mArr[b * NPTS + i];
        negMb[r] = pack2(-mp, -mp);
        mrun[r] = -1e30f;
        Sp[r] = 0ull;
    }

    // Per-warp chunk mask: lane c bounds chunk c for this warp's 4 rows.
    unsigned mask;
    {
        float4 lo = sLo[lane], hi = sHi[lane];
        float hm = sHmax[lane];
        bool act = false;
        #pragma unroll
        for (int r = 0; r < 4; r++) {
            float X0s, d0, X1s, d1, X2s, d2, nm, d3;
            unpack2(X0b[r], X0s, d0);
            unpack2(X1b[r], X1s, d1);
            unpack2(X2b[r], X2s, d2);
            unpack2(negMb[r], nm, d3);
            float ub = hm + nm
                + fmaxf(X0s * lo.x, X0s * hi.x)
                + fmaxf(X1s * lo.y, X1s * hi.y)
                + fmaxf(X2s * lo.z, X2s * hi.z);
            act |= (ub > SKIP_THR);
        }
        mask = __ballot_sync(0xffffffffu, act);
    }

    unsigned int aA = (unsigned int)__cvta_generic_to_shared(sA) + lane * 16u;
    unsigned int aB = (unsigned int)__cvta_generic_to_shared(sB) + lane * 16u;

    for (int it = 0; it < NCHUNK; it++) {
        if (mask & (1u << it)) {
            u64 y0p, y1p, y2p, hp;
            asm("ld.shared.v2.b64 {%0, %1}, [%2];" : "=l"(y0p), "=l"(y1p) : "r"(aA));
            asm("ld.shared.v2.b64 {%0, %1}, [%2];" : "=l"(y2p), "=l"(hp)  : "r"(aB));
            #pragma unroll
            for (int r = 0; r < 4; r++) {
                u64 hpr = add2(hp, negMb[r]);
                u64 w = fma2(X0b[r], y0p, fma2(X1b[r], y1p, fma2(X2b[r], y2p, hpr)));
                float wl, wh; unpack2(w, wl, wh);
                mrun[r] = fmaxf(mrun[r], fmaxf(wl, wh));
                Sp[r] = add2(Sp[r], pack2(ex2f(wl), ex2f(wh)));
            }
        }
        aA += 512u; aB += 512u;
    }

    float S[4];
    #pragma unroll
    for (int r = 0; r < 4; r++) {
        float sl, sh; unpack2(Sp[r], sl, sh);
        S[r] = sl + sh;
        #pragma unroll
        for (int o = 16; o; o >>= 1) {
            S[r]    += __shfl_xor_sync(0xffffffffu, S[r], o);
            mrun[r]  = fmaxf(mrun[r], __shfl_xor_sync(0xffffffffu, mrun[r], o));
        }
    }
    if (lane == 0) {
        #pragma unroll
        for (int r = 0; r < 4; r++) {
            int i = row0 + r;
            float x0 = rp[3*i], x1 = rp[3*i+1], x2 = rp[3*i+2];
            float xx = x0*x0 + x1*x1 + x2*x2;
            float nm, d; unpack2(negMb[r], nm, d);
            float mp = -nm;
            float Sv = fmaxf(S[r], 1e-38f);
            outPot[b * NPTS + i] = ACONST - EPSLN2 * (mp + __log2f(Sv)) + xx;
            mArr[b * NPTS + i]   = mp + mrun[r];
        }
    }
}

// dist_i = N * sum_j 2^((f_i + g_j - C_ij)*K) * C_ij ; AABB skip, 4 rows/warp
__global__ __launch_bounds__(NTHREADS, 2)
void dist_kernel()
{
    __shared__ float4 sCol[NPTS];
    __shared__ float  sYY[NPTS];
    __shared__ float  sHm[64];      // half-chunk maxima of c.w
    __shared__ float4 sLo[NCHUNK], sHi[NCHUNK];
    __shared__ float  wsum[16];

    const int b = blockIdx.y, tid = threadIdx.x;
    const int warp = tid >> 5, lane = tid & 31;

    if (tid < NCHUNK) {
        sLo[tid] = g_lo2[b * NCHUNK + tid];
        sHi[tid] = g_hi2[b * NCHUNK + tid];
    }

    const float* cp = g_p2 + b * NPTS * 3;
    #pragma unroll
    for (int k = 0; k < 4; k++) {
        int j = tid + k * NTHREADS;
        float y0 = cp[3*j], y1 = cp[3*j+1], y2 = cp[3*j+2];
        float yy = y0*y0 + y1*y1 + y2*y2;
        float hK = (g_g[b * NPTS + j] - yy) * KLOG;
        sYY[j] = yy;
        sCol[j] = make_float4(y0, y1, y2, hK);
        float hm = hK;
        #pragma unroll
        for (int o = 16; o; o >>= 1)
            hm = fmaxf(hm, __shfl_xor_sync(0xffffffffu, hm, o));
        if (lane == 0) sHm[warp + k * 16] = hm;   // half-chunk (32 j)
    }
    __syncthreads();

    const int row0 = blockIdx.x * FAST_ROWS_CTA + warp * 4;
    const float* rp = g_p1 + b * NPTS * 3;

    float X0[4], X1[4], X2[4], xx[4], cr[4], acc[4];
    #pragma unroll
    for (int r = 0; r < 4; r++) {
        int i = row0 + r;
        float x0 = rp[3*i], x1 = rp[3*i+1], x2 = rp[3*i+2];
        xx[r] = x0*x0 + x1*x1 + x2*x2;
        X0[r] = 2.0f*KLOG*x0;
        X1[r] = 2.0f*KLOG*x1;
        X2[r] = 2.0f*KLOG*x2;
        cr[r] = (g_f[b * NPTS + i] - xx[r]) * KLOG;
        acc[r] = 0.0f;
    }

    unsigned mask;
    {
        float4 lo = sLo[lane], hi = sHi[lane];
        float hm = fmaxf(sHm[2 * lane], sHm[2 * lane + 1]);
        bool act = false;
        #pragma unroll
        for (int r = 0; r < 4; r++) {
            float ub = hm + cr[r]
                + fmaxf(X0[r] * lo.x, X0[r] * hi.x)
                + fmaxf(X1[r] * lo.y, X1[r] * hi.y)
                + fmaxf(X2[r] * lo.z, X2[r] * hi.z);
            act |= (ub > SKIP_THR);
        }
        mask = __ballot_sync(0xffffffffu, act);
    }

    for (int c = 0; c < NCHUNK; c++) {
        if (!(mask & (1u << c))) continue;
        #pragma unroll
        for (int s = 0; s < 2; s++) {
            int j = c * 64 + s * 32 + lane;
            float4 col = sCol[j];
            float yy = sYY[j];
            #pragma unroll
            for (int r = 0; r < 4; r++) {
                float t = fmaf(X0[r], col.x, fmaf(X1[r], col.y, X2[r] * col.z));
                float p = ex2f(t + col.w + cr[r]);
                float C = fmaf(-EPSLN2, t, xx[r] + yy);
                acc[r] = fmaf(p, C, acc[r]);
            }
        }
    }
    #pragma unroll
    for (int r = 0; r < 4; r++) {
        #pragma unroll
        for (int o = 16; o; o >>= 1)
            acc[r] += __shfl_xor_sync(0xffffffffu, acc[r], o);
    }

    if (lane == 0) {
        float s = 0.0f;
        #pragma unroll
        for (int r = 0; r < 4; r++)
            s += sqrtf(fmaxf(acc[r] * (float)NPTS, 0.0f));
        wsum[warp] = s;
    }
    __syncthreads();
    if (tid == 0) {
        float s = 0.0f;
        #pragma unroll
        for (int w = 0; w < 16; w++) s += wsum[w];
        g_partial[b * FAST_CHUNKS + blockIdx.x] = s;
    }
}

__global__ void final_kernel(float* __restrict__ out) {
    __shared__ float s[BB * FAST_CHUNKS];
    int tid = threadIdx.x;
    s[tid] = g_partial[tid];
    __syncthreads();
    for (int o = (BB * FAST_CHUNKS) / 2; o; o >>= 1) {
        if (tid < o) s[tid] += s[tid + o];
        __syncthreads();
    }
    if (tid == 0) out[0] = s[0] * (1.0f / (BB * NPTS));
}

extern "C" void kernel_launch(void* const* d_in, const int* in_sizes, int n_in,
                              void* d_out, int out_size)
{
    const float* pcs1 = (const float*)d_in[0];
    const float* pcs2 = (const float*)d_in[1];
    float* out = (float*)d_out;

    init_kernel<<<(BB * NPTS + NTHREADS - 1) / NTHREADS, NTHREADS>>>();
    sort_kernel<<<BB, NTHREADS>>>(pcs1, 0);
    sort_kernel<<<BB, NTHREADS>>>(pcs2, 1);

    dim3 gridW(WARM_CHUNKS, BB);
    for (int it = 0; it < 2; it++) {
        sink_warm<<<gridW, NTHREADS>>>(0);
        sink_warm<<<gridW, NTHREADS>>>(1);
    }
    dim3 gridF(FAST_CHUNKS, BB);
    for (int it = 2; it < 50; it++) {
        sink_fast<<<gridF, NTHREADS>>>(0);
        sink_fast<<<gridF, NTHREADS>>>(1);
    }
    sink_fast<<<gridF, NTHREADS>>>(0);

    dist_kernel<<<gridF, NTHREADS>>>();
    final_kernel<<<1, BB * FAST_CHUNKS>>>(out);
}

// round 8
// speedup vs baseline: 1.0990x; 1.0990x over previous
#include <cuda_runtime.h>
#include <math.h>

#define BB 8
#define NPTS 2048
#define NPAIR 1024
#define NTHREADS 512
#define ROWS_PER_CTA 128          // 16 warps * 8 rows
#define CHUNKS 16                 // grid.x = 2048 / 128
#define NCHUNK 32                 // j-chunks of 64 points

// eps = 0.005
#define KLOG 288.53900817779268f          // log2(e)/eps
#define INV2K 0.0017328679513998633f      // 1/(2*KLOG)
#define EPSLN2 0.0034657359027997266f     // eps*ln2
#define ACONST (-0.038123094930796993f)   // eps*log(1/N)
#define SKIP_THR (-30.0f)

typedef unsigned long long u64;

__device__ __forceinline__ float ex2f(float x) {
    float r;
    asm("ex2.approx.ftz.f32 %0, %1;" : "=f"(r) : "f"(x));
    return r;
}
__device__ __forceinline__ u64 pack2(float lo, float hi) {
    u64 r; asm("mov.b64 %0, {%1, %2};" : "=l"(r) : "f"(lo), "f"(hi)); return r;
}
__device__ __forceinline__ void unpack2(u64 v, float& lo, float& hi) {
    asm("mov.b64 {%0, %1}, %2;" : "=f"(lo), "=f"(hi) : "l"(v));
}
__device__ __forceinline__ u64 fma2(u64 a, u64 b, u64 c) {
    u64 r; asm("fma.rn.f32x2 %0, %1, %2, %3;" : "=l"(r) : "l"(a), "l"(b), "l"(c)); return r;
}
__device__ __forceinline__ u64 add2(u64 a, u64 b) {
    u64 r; asm("add.rn.f32x2 %0, %1, %2;" : "=l"(r) : "l"(a), "l"(b)); return r;
}

// Persistent scratch
__device__ float  g_p1[BB * NPTS * 3];
__device__ float  g_p2[BB * NPTS * 3];
__device__ float4 g_lo1[BB * NCHUNK], g_hi1[BB * NCHUNK];
__device__ float4 g_lo2[BB * NCHUNK], g_hi2[BB * NCHUNK];
__device__ float  g_f[BB * NPTS];
__device__ float  g_g[BB * NPTS];
__device__ float  g_mf[BB * NPTS];
__device__ float  g_mg[BB * NPTS];
__device__ float  g_partial[BB * CHUNKS];

__global__ void init_kernel() {
    int i = blockIdx.x * blockDim.x + threadIdx.x;
    if (i < BB * NPTS) g_g[i] = 0.0f;
}

__device__ __forceinline__ unsigned expand_bits(unsigned v) {
    v &= 0x3FFu;
    v = (v | (v << 16)) & 0x030000FFu;
    v = (v | (v << 8))  & 0x0300F00Fu;
    v = (v | (v << 4))  & 0x030C30C3u;
    v = (v | (v << 2))  & 0x09249249u;
    return v;
}

// One CTA per batch: Morton bitonic sort + per-chunk AABB.
__global__ __launch_bounds__(NTHREADS, 1)
void sort_kernel(const float* __restrict__ pts, int side)
{
    __shared__ unsigned key[NPTS];
    __shared__ int      idx[NPTS];
    const int b = blockIdx.x, tid = threadIdx.x;
    const float* p = pts + b * NPTS * 3;

    for (int j = tid; j < NPTS; j += NTHREADS) {
        float x = p[3*j], y = p[3*j+1], z = p[3*j+2];
        unsigned qx = (unsigned)fminf(fmaxf(x * 1024.0f, 0.0f), 1023.0f);
        unsigned qy = (unsigned)fminf(fmaxf(y * 1024.0f, 0.0f), 1023.0f);
        unsigned qz = (unsigned)fminf(fmaxf(z * 1024.0f, 0.0f), 1023.0f);
        key[j] = expand_bits(qx) | (expand_bits(qy) << 1) | (expand_bits(qz) << 2);
        idx[j] = j;
    }
    __syncthreads();

    for (int k2 = 2; k2 <= NPTS; k2 <<= 1) {
        for (int j2 = k2 >> 1; j2 > 0; j2 >>= 1) {
            for (int i = tid; i < NPTS; i += NTHREADS) {
                int l = i ^ j2;
                if (l > i) {
                    bool up = ((i & k2) == 0);
                    unsigned ki = key[i], kl = key[l];
                    bool swp = up ? (ki > kl) : (ki < kl);
                    if (swp) {
                        key[i] = kl; key[l] = ki;
                        int t = idx[i]; idx[i] = idx[l]; idx[l] = t;
                    }
                }
            }
            __syncthreads();
        }
    }

    float* out = (side ? g_p2 : g_p1) + b * NPTS * 3;
    for (int k = tid; k < NPTS; k += NTHREADS) {
        int s = idx[k];
        out[3*k]   = p[3*s];
        out[3*k+1] = p[3*s+1];
        out[3*k+2] = p[3*s+2];
    }
    __syncthreads();

    if (tid < NCHUNK) {
        float lx = 1e30f, ly = 1e30f, lz = 1e30f;
        float hx = -1e30f, hy = -1e30f, hz = -1e30f;
        for (int k = 0; k < 64; k++) {
            int j = tid * 64 + k;
            float x = out[3*j], y = out[3*j+1], z = out[3*j+2];
            lx = fminf(lx, x); hx = fmaxf(hx, x);
            ly = fminf(ly, y); hy = fmaxf(hy, y);
            lz = fminf(lz, z); hz = fmaxf(hz, z);
        }
        float4* glo = side ? g_lo2 : g_lo1;
        float4* ghi = side ? g_hi2 : g_hi1;
        glo[b * NCHUNK + tid] = make_float4(lx, ly, lz, 0.0f);
        ghi[b * NCHUNK + tid] = make_float4(hx, hy, hz, 0.0f);
    }
}

// ---------- Warmup: rigorous two-pass half-step (emits row max) ----------
__global__ __launch_bounds__(NTHREADS, 1)
void sink_warm(int dir)
{
    __shared__ float4 sA[NPAIR];
    __shared__ float4 sB[NPAIR];

    const int b = blockIdx.y, tid = threadIdx.x;
    const float* rowPts = dir ? g_p2 : g_p1;
    const float* colPts = dir ? g_p1 : g_p2;
    const float* colPot = dir ? g_f  : g_g;
    float*       outPot = dir ? g_g  : g_f;
    float*       outM   = dir ? g_mg : g_mf;

    const float* cp = colPts + b * NPTS * 3;
    const float* gp = colPot + b * NPTS;
    for (int p = tid; p < NPAIR; p += NTHREADS) {
        int j = 2 * p;
        float a0 = cp[3*j],   a1 = cp[3*j+1], a2 = cp[3*j+2];
        float b0 = cp[3*j+3], b1 = cp[3*j+4], b2 = cp[3*j+5];
        float ha = (gp[j]   - (a0*a0 + a1*a1 + a2*a2)) * KLOG;
        float hb = (gp[j+1] - (b0*b0 + b1*b1 + b2*b2)) * KLOG;
        sA[p] = make_float4(a0, b0, a1, b1);
        sB[p] = make_float4(a2, b2, ha, hb);
    }
    __syncthreads();

    const int warp = tid >> 5, lane = tid & 31;
    const int row0 = blockIdx.x * ROWS_PER_CTA + warp * 8;
    const float* rp = rowPts + b * NPTS * 3;

    u64 X0b[8], X1b[8], X2b[8];
    float xx[8], m[8];
    #pragma unroll
    for (int r = 0; r < 8; r++) {
        int i = row0 + r;
        float x0 = rp[3*i], x1 = rp[3*i+1], x2 = rp[3*i+2];
        xx[r] = x0*x0 + x1*x1 + x2*x2;
        X0b[r] = pack2(2.0f*KLOG*x0, 2.0f*KLOG*x0);
        X1b[r] = pack2(2.0f*KLOG*x1, 2.0f*KLOG*x1);
        X2b[r] = pack2(2.0f*KLOG*x2, 2.0f*KLOG*x2);
        m[r]  = -1e30f;
    }

    unsigned int aA0 = (unsigned int)__cvta_generic_to_shared(sA) + lane * 16u;
    unsigned int aB0 = (unsigned int)__cvta_generic_to_shared(sB) + lane * 16u;

    {
        unsigned int aA = aA0, aB = aB0;
        #pragma unroll 2
        for (int it = 0; it < NPAIR / 32; it++) {
            u64 y0p, y1p, y2p, hp;
            asm("ld.shared.v2.b64 {%0, %1}, [%2];" : "=l"(y0p), "=l"(y1p) : "r"(aA));
            asm("ld.shared.v2.b64 {%0, %1}, [%2];" : "=l"(y2p), "=l"(hp)  : "r"(aB));
            #pragma unroll
            for (int r = 0; r < 8; r++) {
                u64 w = fma2(X0b[r], y0p, fma2(X1b[r], y1p, fma2(X2b[r], y2p, hp)));
                float wl, wh; unpack2(w, wl, wh);
                m[r] = fmaxf(m[r], fmaxf(wl, wh));
            }
            aA += 512u; aB += 512u;
        }
    }

    u64 mnegb[8], Sp[8];
    #pragma unroll
    for (int r = 0; r < 8; r++) {
        #pragma unroll
        for (int o = 16; o; o >>= 1)
            m[r] = fmaxf(m[r], __shfl_xor_sync(0xffffffffu, m[r], o));
        mnegb[r] = pack2(-m[r], -m[r]);
        Sp[r] = 0ull;
    }

    {
        unsigned int aA = aA0, aB = aB0;
        #pragma unroll 2
        for (int it = 0; it < NPAIR / 32; it++) {
            u64 y0p, y1p, y2p, hp;
            asm("ld.shared.v2.b64 {%0, %1}, [%2];" : "=l"(y0p), "=l"(y1p) : "r"(aA));
            asm("ld.shared.v2.b64 {%0, %1}, [%2];" : "=l"(y2p), "=l"(hp)  : "r"(aB));
            #pragma unroll
            for (int r = 0; r < 8; r++) {
                u64 w = fma2(X0b[r], y0p, fma2(X1b[r], y1p, fma2(X2b[r], y2p, hp)));
                u64 t = add2(w, mnegb[r]);
                float tl, th; unpack2(t, tl, th);
                Sp[r] = add2(Sp[r], pack2(ex2f(tl), ex2f(th)));
            }
            aA += 512u; aB += 512u;
        }
    }

    float S[8];
    #pragma unroll
    for (int r = 0; r < 8; r++) {
        float sl, sh; unpack2(Sp[r], sl, sh);
        S[r] = sl + sh;
        #pragma unroll
        for (int o = 16; o; o >>= 1)
            S[r] += __shfl_xor_sync(0xffffffffu, S[r], o);
    }
    if (lane == 0) {
        #pragma unroll
        for (int r = 0; r < 8; r++) {
            outPot[b * NPTS + row0 + r] = ACONST - EPSLN2 * (m[r] + __log2f(S[r])) + xx[r];
            outM[b * NPTS + row0 + r]   = m[r];
        }
    }
}

// ---------- Fast: single-pass, carried max, exact point-to-box chunk skip ----------
__global__ __launch_bounds__(NTHREADS, 1)
void sink_fast(int dir)
{
    __shared__ float4 sA[NPAIR];
    __shared__ float4 sB[NPAIR];
    __shared__ float  sGmax[NCHUNK];     // per-chunk max of raw colPot
    __shared__ float4 sLo[NCHUNK], sHi[NCHUNK];

    const int b = blockIdx.y, tid = threadIdx.x;
    const float* rowPts = dir ? g_p2 : g_p1;
    const float* colPts = dir ? g_p1 : g_p2;
    const float* colPot = dir ? g_f  : g_g;
    float*       outPot = dir ? g_g  : g_f;
    float*       mArr   = dir ? g_mg : g_mf;
    const float4* glo = dir ? g_lo1 : g_lo2;   // columns' boxes
    const float4* ghi = dir ? g_hi1 : g_hi2;

    const int warp = tid >> 5, lane = tid & 31;

    if (tid < NCHUNK) {
        sLo[tid] = glo[b * NCHUNK + tid];
        sHi[tid] = ghi[b * NCHUNK + tid];
    }

    const float* cp = colPts + b * NPTS * 3;
    const float* gp = colPot + b * NPTS;
    #pragma unroll
    for (int k = 0; k < 2; k++) {
        int p = tid + k * NTHREADS;      // warp w covers pairs of chunk (w + 16k)
        int j = 2 * p;
        float ga = gp[j], gb = gp[j+1];
        float a0 = cp[3*j],   a1 = cp[3*j+1], a2 = cp[3*j+2];
        float b0 = cp[3*j+3], b1 = cp[3*j+4], b2 = cp[3*j+5];
        float ha = (ga - (a0*a0 + a1*a1 + a2*a2)) * KLOG;
        float hb = (gb - (b0*b0 + b1*b1 + b2*b2)) * KLOG;
        sA[p] = make_float4(a0, b0, a1, b1);
        sB[p] = make_float4(a2, b2, ha, hb);
        float gm = fmaxf(ga, gb);
        #pragma unroll
        for (int o = 16; o; o >>= 1)
            gm = fmaxf(gm, __shfl_xor_sync(0xffffffffu, gm, o));
        if (lane == 0) sGmax[warp + k * 16] = gm;
    }
    __syncthreads();

    const int row0 = blockIdx.x * ROWS_PER_CTA + warp * 8;
    const float* rp = rowPts + b * NPTS * 3;

    u64 X0b[8], X1b[8], X2b[8], negMb[8], Sp[8];
    float mrun[8];
    #pragma unroll
    for (int r = 0; r < 8; r++) {
        int i = row0 + r;
        float x0 = rp[3*i], x1 = rp[3*i+1], x2 = rp[3*i+2];
        X0b[r] = pack2(2.0f*KLOG*x0, 2.0f*KLOG*x0);
        X1b[r] = pack2(2.0f*KLOG*x1, 2.0f*KLOG*x1);
        X2b[r] = pack2(2.0f*KLOG*x2, 2.0f*KLOG*x2);
        float mp = mArr[b * NPTS + i];
        negMb[r] = pack2(-mp, -mp);
        mrun[r] = -1e30f;
        Sp[r] = 0ull;
    }

    // Chunk mask: lane c bounds chunk c for this warp's 8 rows.
    // ub_r = K*(gmax_c + xx_r - mindist^2(x_r, box_c)) - mp_r
    unsigned mask;
    {
        float4 lo = sLo[lane], hi = sHi[lane];
        float gm = sGmax[lane];
        bool act = false;
        #pragma unroll
        for (int r = 0; r < 8; r++) {
            float X0s, X1s, X2s, nm, d;
            unpack2(X0b[r], X0s, d);
            unpack2(X1b[r], X1s, d);
            unpack2(X2b[r], X2s, d);
            unpack2(negMb[r], nm, d);
            float x0 = X0s * INV2K, x1 = X1s * INV2K, x2 = X2s * INV2K;
            float dx = fmaxf(fmaxf(lo.x - x0, x0 - hi.x), 0.0f);
            float dy = fmaxf(fmaxf(lo.y - x1, x1 - hi.y), 0.0f);
            float dz = fmaxf(fmaxf(lo.z - x2, x2 - hi.z), 0.0f);
            float d2 = dx*dx + dy*dy + dz*dz;
            float xx = x0*x0 + x1*x1 + x2*x2;
            float ub = KLOG * (gm + xx - d2) + nm;
            act |= (ub > SKIP_THR);
        }
        mask = __ballot_sync(0xffffffffu, act);
    }

    unsigned int aA = (unsigned int)__cvta_generic_to_shared(sA) + lane * 16u;
    unsigned int aB = (unsigned int)__cvta_generic_to_shared(sB) + lane * 16u;

    for (int it = 0; it < NCHUNK; it++) {
        if (mask & (1u << it)) {
            u64 y0p, y1p, y2p, hp;
            asm("ld.shared.v2.b64 {%0, %1}, [%2];" : "=l"(y0p), "=l"(y1p) : "r"(aA));
            asm("ld.shared.v2.b64 {%0, %1}, [%2];" : "=l"(y2p), "=l"(hp)  : "r"(aB));
            #pragma unroll
            for (int r = 0; r < 8; r++) {
                u64 hpr = add2(hp, negMb[r]);
                u64 w = fma2(X0b[r], y0p, fma2(X1b[r], y1p, fma2(X2b[r], y2p, hpr)));
                float wl, wh; unpack2(w, wl, wh);
                mrun[r] = fmaxf(mrun[r], fmaxf(wl, wh));
                Sp[r] = add2(Sp[r], pack2(ex2f(wl), ex2f(wh)));
            }
        }
        aA += 512u; aB += 512u;
    }

    float S[8];
    #pragma unroll
    for (int r = 0; r < 8; r++) {
        float sl, sh; unpack2(Sp[r], sl, sh);
        S[r] = sl + sh;
        #pragma unroll
        for (int o = 16; o; o >>= 1) {
            S[r]    += __shfl_xor_sync(0xffffffffu, S[r], o);
            mrun[r]  = fmaxf(mrun[r], __shfl_xor_sync(0xffffffffu, mrun[r], o));
        }
    }
    if (lane == 0) {
        #pragma unroll
        for (int r = 0; r < 8; r++) {
            int i = row0 + r;
            float x0 = rp[3*i], x1 = rp[3*i+1], x2 = rp[3*i+2];
            float xx = x0*x0 + x1*x1 + x2*x2;
            float nm, d; unpack2(negMb[r], nm, d);
            float mp = -nm;
            float Sv = fmaxf(S[r], 1e-38f);
            outPot[b * NPTS + i] = ACONST - EPSLN2 * (mp + __log2f(Sv)) + xx;
            mArr[b * NPTS + i]   = mp + mrun[r];
        }
    }
}

// dist_i = N * sum_j 2^(K(f_i+g_j-C_ij)) * C_ij ; same chunk skip
__global__ __launch_bounds__(NTHREADS, 1)
void dist_kernel()
{
    __shared__ float4 sCol[NPTS];
    __shared__ float  sYY[NPTS];
    __shared__ float  sGm[64];      // half-chunk maxima of g
    __shared__ float4 sLo[NCHUNK], sHi[NCHUNK];
    __shared__ float  wsum[16];

    const int b = blockIdx.y, tid = threadIdx.x;
    const int warp = tid >> 5, lane = tid & 31;

    if (tid < NCHUNK) {
        sLo[tid] = g_lo2[b * NCHUNK + tid];
        sHi[tid] = g_hi2[b * NCHUNK + tid];
    }

    const float* cp = g_p2 + b * NPTS * 3;
    #pragma unroll
    for (int k = 0; k < 4; k++) {
        int j = tid + k * NTHREADS;
        float gv = g_g[b * NPTS + j];
        float y0 = cp[3*j], y1 = cp[3*j+1], y2 = cp[3*j+2];
        float yy = y0*y0 + y1*y1 + y2*y2;
        sYY[j] = yy;
        sCol[j] = make_float4(y0, y1, y2, (gv - yy) * KLOG);
        float gm = gv;
        #pragma unroll
        for (int o = 16; o; o >>= 1)
            gm = fmaxf(gm, __shfl_xor_sync(0xffffffffu, gm, o));
        if (lane == 0) sGm[warp + k * 16] = gm;   // half-chunk (32 j)
    }
    __syncthreads();

    const int row0 = blockIdx.x * ROWS_PER_CTA + warp * 8;
    const float* rp = g_p1 + b * NPTS * 3;

    float X0[8], X1[8], X2[8], xx[8], cr[8], acc[8], fK[8];
    #pragma unroll
    for (int r = 0; r < 8; r++) {
        int i = row0 + r;
        float x0 = rp[3*i], x1 = rp[3*i+1], x2 = rp[3*i+2];
        xx[r] = x0*x0 + x1*x1 + x2*x2;
        X0[r] = 2.0f*KLOG*x0;
        X1[r] = 2.0f*KLOG*x1;
        X2[r] = 2.0f*KLOG*x2;
        float fv = g_f[b * NPTS + i];
        fK[r] = fv * KLOG;
        cr[r] = (fv - xx[r]) * KLOG;
        acc[r] = 0.0f;
    }

    unsigned mask;
    {
        float4 lo = sLo[lane], hi = sHi[lane];
        float gm = fmaxf(sGm[2 * lane], sGm[2 * lane + 1]);
        bool act = false;
        #pragma unroll
        for (int r = 0; r < 8; r++) {
            float x0 = X0[r] * INV2K, x1 = X1[r] * INV2K, x2 = X2[r] * INV2K;
            float dx = fmaxf(fmaxf(lo.x - x0, x0 - hi.x), 0.0f);
            float dy = fmaxf(fmaxf(lo.y - x1, x1 - hi.y), 0.0f);
            float dz = fmaxf(fmaxf(lo.z - x2, x2 - hi.z), 0.0f);
            float d2 = dx*dx + dy*dy + dz*dz;
            float ub = fK[r] + KLOG * (gm - d2);   // K(f_i + gmax - mind2)
            act |= (ub > SKIP_THR);
        }
        mask = __ballot_sync(0xffffffffu, act);
    }

    for (int c = 0; c < NCHUNK; c++) {
        if (!(mask & (1u << c))) continue;
        #pragma unroll
        for (int s = 0; s < 2; s++) {
            int j = c * 64 + s * 32 + lane;
            float4 col = sCol[j];
            float yy = sYY[j];
            #pragma unroll
            for (int r = 0; r < 8; r++) {
                float t = fmaf(X0[r], col.x, fmaf(X1[r], col.y, X2[r] * col.z));
                float p = ex2f(t + col.w + cr[r]);
                float C = fmaf(-EPSLN2, t, xx[r] + yy);
                acc[r] = fmaf(p, C, acc[r]);
            }
        }
    }
    #pragma unroll
    for (int r = 0; r < 8; r++) {
        #pragma unroll
        for (int o = 16; o; o >>= 1)
            acc[r] += __shfl_xor_sync(0xffffffffu, acc[r], o);
    }

    if (lane == 0) {
        float s = 0.0f;
        #pragma unroll
        for (int r = 0; r < 8; r++)
            s += sqrtf(fmaxf(acc[r] * (float)NPTS, 0.0f));
        wsum[warp] = s;
    }
    __syncthreads();
    if (tid == 0) {
        float s = 0.0f;
        #pragma unroll
        for (int w = 0; w < 16; w++) s += wsum[w];
        g_partial[b * CHUNKS + blockIdx.x] = s;
    }
}

__global__ void final_kernel(float* __restrict__ out) {
    __shared__ float s[BB * CHUNKS];
    int tid = threadIdx.x;
    s[tid] = g_partial[tid];
    __syncthreads();
    for (int o = (BB * CHUNKS) / 2; o; o >>= 1) {
        if (tid < o) s[tid] += s[tid + o];
        __syncthreads();
    }
    if (tid == 0) out[0] = s[0] * (1.0f / (BB * NPTS));
}

extern "C" void kernel_launch(void* const* d_in, const int* in_sizes, int n_in,
                              void* d_out, int out_size)
{
    const float* pcs1 = (const float*)d_in[0];
    const float* pcs2 = (const float*)d_in[1];
    float* out = (float*)d_out;

    init_kernel<<<(BB * NPTS + NTHREADS - 1) / NTHREADS, NTHREADS>>>();
    sort_kernel<<<BB, NTHREADS>>>(pcs1, 0);
    sort_kernel<<<BB, NTHREADS>>>(pcs2, 1);

    dim3 grid(CHUNKS, BB);
    for (int it = 0; it < 2; it++) {
        sink_warm<<<grid, NTHREADS>>>(0);
        sink_warm<<<grid, NTHREADS>>>(1);
    }
    for (int it = 2; it < 50; it++) {
        sink_fast<<<grid, NTHREADS>>>(0);
        sink_fast<<<grid, NTHREADS>>>(1);
    }
    sink_fast<<<grid, NTHREADS>>>(0);

    dist_kernel<<<grid, NTHREADS>>>();
    final_kernel<<<1, BB * CHUNKS>>>(out);
}